// round 13
// baseline (speedup 1.0000x reference)
#include <cuda_runtime.h>
#include <math.h>

#define NN 100000
#define NE 3200000
#define FIN 512
#define HD 16
#define NC 40

#define RPB 256    // rows per gemm block
#define TPB_G 128  // gemm threads per block (2 rows/thread)
#define CH 16      // k-chunk size (4 float4)
#define QPAD 5     // 4 float4 per row + 1 pad -> conflict-free LDS.128

typedef unsigned long long ull;

// ---------------- device scratch (static: no runtime alloc) ----------------
__device__ int   g_deg[NN];          // zero-init by loader; restored each run
__device__ int   g_off[NN + 1];
__device__ int   g_cur[NN];
__device__ int   g_bsum[128];
__device__ int   g_ctr = 0;          // scan arrival counter (self-restoring)
__device__ int   g_ctr2 = 0;         // scan exit counter
__device__ int   g_flag = 0;         // scan middle-phase flag
__device__ int   g_src[NE];
__device__ float g_dinv[NN];
__device__ float g_h1s[NN * HD];
__device__ float g_rs[NN * HD];

// ---------------- f32x2 packed math helpers ----------------
__device__ __forceinline__ ull pk2(float lo, float hi) {
    ull r;
    asm("mov.b64 %0, {%1, %2};" : "=l"(r) : "f"(lo), "f"(hi));
    return r;
}
__device__ __forceinline__ ull fma2(ull a, ull b, ull c) {
    ull d;
    asm("fma.rn.f32x2 %0, %1, %2, %3;" : "=l"(d) : "l"(a), "l"(b), "l"(c));
    return d;
}
__device__ __forceinline__ float2 upk2(ull p) {
    float2 v;
    asm("mov.b64 {%0, %1}, %2;" : "=f"(v.x), "=f"(v.y) : "l"(p));
    return v;
}

// Per-block int32/int64 detection: int64 ids < 2^31 => odd 32-bit words all 0.
__device__ __forceinline__ int detect_is64(const void* ei, int tid) {
    __shared__ int s64;
    if (tid < 32) {
        int w = ((const int*)ei)[2 * tid + 1];
        unsigned nz = __ballot_sync(0xffffffffu, w != 0);
        if (tid == 0) s64 = (nz == 0) ? 1 : 0;
    }
    __syncthreads();
    return s64;
}

// 4 edges per thread histogram of dst (col) array.
__global__ void k_hist(const void* __restrict__ ei) {
    int tid = threadIdx.x;
    int is64 = detect_is64(ei, tid);
    int t = blockIdx.x * 256 + tid;
    if (t >= NE / 4) return;
    int c0, c1, c2, c3;
    if (is64) {
        const longlong2* p = (const longlong2*)((const long long*)ei + NE);
        longlong2 a = p[2 * t];
        longlong2 b = p[2 * t + 1];
        c0 = (int)a.x; c1 = (int)a.y; c2 = (int)b.x; c3 = (int)b.y;
    } else {
        int4 a = ((const int4*)((const int*)ei + NE))[t];
        c0 = a.x; c1 = a.y; c2 = a.z; c3 = a.w;
    }
    atomicAdd(&g_deg[c0], 1);
    atomicAdd(&g_deg[c1], 1);
    atomicAdd(&g_deg[c2], 1);
    atomicAdd(&g_deg[c3], 1);
}

// Single-kernel full scan (single wave, 98 blocks). Re-zeros g_deg and its
// own state (ctr/ctr2/flag) so every graph replay starts clean.
__global__ __launch_bounds__(1024) void k_scan_all() {
    int b = blockIdx.x;
    int i = b * 1024 + threadIdx.x;
    int val = (i < NN) ? g_deg[i] : 0;
    int lane = threadIdx.x & 31, wid = threadIdx.x >> 5;
    int x = val;
#pragma unroll
    for (int o = 1; o < 32; o <<= 1) {
        int y = __shfl_up_sync(0xffffffffu, x, o);
        if (lane >= o) x += y;
    }
    __shared__ int wsum[32];
    __shared__ int amLast;
    if (lane == 31) wsum[wid] = x;
    __syncthreads();
    if (wid == 0) {
        int w = wsum[lane];
#pragma unroll
        for (int o = 1; o < 32; o <<= 1) {
            int y = __shfl_up_sync(0xffffffffu, w, o);
            if (lane >= o) w += y;
        }
        wsum[lane] = w;
    }
    __syncthreads();
    int incl = x + (wid > 0 ? wsum[wid - 1] : 0);
    if (threadIdx.x == 1023) g_bsum[b] = incl;
    __syncthreads();
    if (threadIdx.x == 0) {
        __threadfence();
        amLast = (atomicAdd(&g_ctr, 1) == gridDim.x - 1);
    }
    __syncthreads();
    if (amLast) {
        if (threadIdx.x == 0) __threadfence();
        __syncthreads();
        if (threadIdx.x < 32) {
            int nb = gridDim.x;
            int base = threadIdx.x * 4;
            int v0 = (base + 0 < nb) ? g_bsum[base + 0] : 0;
            int v1 = (base + 1 < nb) ? g_bsum[base + 1] : 0;
            int v2 = (base + 2 < nb) ? g_bsum[base + 2] : 0;
            int v3 = (base + 3 < nb) ? g_bsum[base + 3] : 0;
            int s0 = v0, s1 = s0 + v1, s2 = s1 + v2, s3 = s2 + v3;
            int tot = s3;
            int xs = tot;
#pragma unroll
            for (int o = 1; o < 32; o <<= 1) {
                int y = __shfl_up_sync(0xffffffffu, xs, o);
                if (lane >= o) xs += y;
            }
            int excl = xs - tot;
            g_bsum[base + 0] = s0 + excl;
            g_bsum[base + 1] = s1 + excl;
            g_bsum[base + 2] = s2 + excl;
            g_bsum[base + 3] = s3 + excl;
            __syncwarp();
            if (threadIdx.x == 0) {
                int one = 1;
                asm volatile("st.release.gpu.b32 [%0], %1;" ::"l"(&g_flag),
                             "r"(one) : "memory");
            }
        }
    }
    if (threadIdx.x == 0) {
        int f;
        do {
            asm volatile("ld.acquire.gpu.b32 %0, [%1];" : "=r"(f)
                         : "l"(&g_flag) : "memory");
        } while (f == 0);
    }
    __syncthreads();
    int add = (b > 0) ? g_bsum[b - 1] : 0;
    int fin = incl + add;
    if (i < NN) {
        g_off[i + 1] = fin;
        g_cur[i] = fin - val;
        g_dinv[i] = rsqrtf((float)(val + 1));
        g_deg[i] = 0;  // restore for next replay
    }
    if (i == 0) g_off[0] = 0;
    __syncthreads();
    if (threadIdx.x == 0) {
        if (atomicAdd(&g_ctr2, 1) == gridDim.x - 1) {
            g_ctr = 0;
            g_ctr2 = 0;
            g_flag = 0;
        }
    }
}

// GEMM1 (UNSCALED): 2 rows/thread, k sequential, W warp-uniform in smem,
// x staged row-major in SMEM with register-prefetch pipeline. CH=16 keeps
// smem at 53.2KB -> 4 blocks/SM (16 warps). Side-stream concurrent with CSR.
__global__ __launch_bounds__(TPB_G, 4) void k_gemm1(
    const float* __restrict__ x, const float* __restrict__ W1) {
    extern __shared__ char sm[];
    ull* Ws = (ull*)sm;                            // 4096 ull = 32KB
    float4* sx = (float4*)(sm + FIN * 8 * 8);      // [RPB][QPAD]
    int tid = threadIdx.x;

    const ull* w64 = (const ull*)W1;  // identity packing: pairs of floats
    for (int i = tid; i < FIN * 8; i += TPB_G) Ws[i] = w64[i];

    int base = blockIdx.x * RPB;
    int r0 = base + tid;
    int r1 = base + tid + TPB_G;

    ull acc0[8], acc1[8];
#pragma unroll
    for (int jp = 0; jp < 8; jp++) { acc0[jp] = 0ull; acc1[jp] = 0ull; }

    const float4* x4 = (const float4*)x;

    // staging map: i = tid + it*TPB_G -> row = i>>2, q = i&3 (coalesced LDG)
    int srow[8], sq[8];
    size_t sgoff[8];
#pragma unroll
    for (int it = 0; it < 8; it++) {
        int i = tid + it * TPB_G;
        srow[it] = i >> 2;
        sq[it] = i & 3;
        int gr = min(base + srow[it], NN - 1);
        sgoff[it] = (size_t)gr * 128 + sq[it];
    }

    float4 pf[8];
#pragma unroll
    for (int it = 0; it < 8; it++) pf[it] = x4[sgoff[it]];

    for (int ch = 0; ch < FIN / CH; ch++) {
        __syncthreads();
#pragma unroll
        for (int it = 0; it < 8; it++)
            sx[srow[it] * QPAD + sq[it]] = pf[it];
        if (ch + 1 < FIN / CH) {
#pragma unroll
            for (int it = 0; it < 8; it++)
                pf[it] = x4[sgoff[it] + (size_t)(ch + 1) * 4];
        }
        __syncthreads();

        const ulonglong2* wrow = (const ulonglong2*)&Ws[ch * CH * 8];
#pragma unroll
        for (int k4 = 0; k4 < CH / 4; k4++) {
            float4 xv0 = sx[tid * QPAD + k4];
            float4 xv1 = sx[(tid + TPB_G) * QPAD + k4];
            float xa0[4] = {xv0.x, xv0.y, xv0.z, xv0.w};
            float xa1[4] = {xv1.x, xv1.y, xv1.z, xv1.w};
#pragma unroll
            for (int c = 0; c < 4; c++) {
                ull xp0 = pk2(xa0[c], xa0[c]);
                ull xp1 = pk2(xa1[c], xa1[c]);
#pragma unroll
                for (int jq = 0; jq < 4; jq++) {
                    ulonglong2 wv = wrow[(k4 * 4 + c) * 4 + jq];  // uniform
                    acc0[2 * jq] = fma2(xp0, wv.x, acc0[2 * jq]);
                    acc0[2 * jq + 1] = fma2(xp0, wv.y, acc0[2 * jq + 1]);
                    acc1[2 * jq] = fma2(xp1, wv.x, acc1[2 * jq]);
                    acc1[2 * jq + 1] = fma2(xp1, wv.y, acc1[2 * jq + 1]);
                }
            }
        }
    }

    if (r0 < NN) {
        float4* o4 = (float4*)&g_h1s[(size_t)r0 * HD];
#pragma unroll
        for (int q = 0; q < 4; q++) {
            float2 a = upk2(acc0[2 * q]);
            float2 b = upk2(acc0[2 * q + 1]);
            o4[q] = make_float4(a.x, a.y, b.x, b.y);
        }
    }
    if (r1 < NN) {
        float4* o4 = (float4*)&g_h1s[(size_t)r1 * HD];
#pragma unroll
        for (int q = 0; q < 4; q++) {
            float2 a = upk2(acc1[2 * q]);
            float2 b = upk2(acc1[2 * q + 1]);
            o4[q] = make_float4(a.x, a.y, b.x, b.y);
        }
    }
}

// Apply dinv scaling to h1s. Runs on the side stream after gemm + scan,
// overlapping scatter on the main stream.
__global__ void k_scale() {
    int i = blockIdx.x * 256 + threadIdx.x;
    if (i >= NN * 4) return;
    float dv = g_dinv[i >> 2];
    float4* p = (float4*)g_h1s;
    float4 v = p[i];
    v.x *= dv; v.y *= dv; v.z *= dv; v.w *= dv;
    p[i] = v;
}

// 4 edges per thread scatter (row into CSR slot of col).
__global__ void k_scatter(const void* __restrict__ ei) {
    int tid = threadIdx.x;
    int is64 = detect_is64(ei, tid);
    int t = blockIdx.x * 256 + tid;
    if (t >= NE / 4) return;
    int r0, r1, r2, r3, c0, c1, c2, c3;
    if (is64) {
        const longlong2* pr = (const longlong2*)((const long long*)ei);
        const longlong2* pc = (const longlong2*)((const long long*)ei + NE);
        longlong2 ra = pr[2 * t], rb = pr[2 * t + 1];
        longlong2 ca = pc[2 * t], cb = pc[2 * t + 1];
        r0 = (int)ra.x; r1 = (int)ra.y; r2 = (int)rb.x; r3 = (int)rb.y;
        c0 = (int)ca.x; c1 = (int)ca.y; c2 = (int)cb.x; c3 = (int)cb.y;
    } else {
        int4 ra = ((const int4*)((const int*)ei))[t];
        int4 ca = ((const int4*)((const int*)ei + NE))[t];
        r0 = ra.x; r1 = ra.y; r2 = ra.z; r3 = ra.w;
        c0 = ca.x; c1 = ca.y; c2 = ca.z; c3 = ca.w;
    }
    g_src[atomicAdd(&g_cur[c0], 1)] = r0;
    g_src[atomicAdd(&g_cur[c1], 1)] = r1;
    g_src[atomicAdd(&g_cur[c2], 1)] = r2;
    g_src[atomicAdd(&g_cur[c3], 1)] = r3;
}

// Aggregation 1: rs[v] = relu((sum_in h1s + h1s[v])*dinv[v] + b1) * dinv[v]
__global__ __launch_bounds__(256) void k_agg1(const float* __restrict__ b1) {
    int warp = (blockIdx.x * 256 + threadIdx.x) >> 5;
    if (warp >= NN) return;
    int v = warp;
    int lane = threadIdx.x & 31;
    int slot = lane >> 2;
    int fq = lane & 3;
    const float4* h4 = (const float4*)g_h1s;
    int start = g_off[v], end = g_off[v + 1];
    float4 s = make_float4(0.f, 0.f, 0.f, 0.f);
    float4 s2 = make_float4(0.f, 0.f, 0.f, 0.f);
    int e = start + slot;
    for (; e + 8 < end; e += 16) {
        int sa = g_src[e];
        int sb = g_src[e + 8];
        float4 ha = h4[(size_t)sa * 4 + fq];
        float4 hb = h4[(size_t)sb * 4 + fq];
        s.x += ha.x; s.y += ha.y; s.z += ha.z; s.w += ha.w;
        s2.x += hb.x; s2.y += hb.y; s2.z += hb.z; s2.w += hb.w;
    }
    if (e < end) {
        float4 ha = h4[(size_t)g_src[e] * 4 + fq];
        s.x += ha.x; s.y += ha.y; s.z += ha.z; s.w += ha.w;
    }
    s.x += s2.x; s.y += s2.y; s.z += s2.z; s.w += s2.w;
#pragma unroll
    for (int o = 4; o <= 16; o <<= 1) {
        s.x += __shfl_xor_sync(0xffffffffu, s.x, o);
        s.y += __shfl_xor_sync(0xffffffffu, s.y, o);
        s.z += __shfl_xor_sync(0xffffffffu, s.z, o);
        s.w += __shfl_xor_sync(0xffffffffu, s.w, o);
    }
    float4 self = h4[(size_t)v * 4 + fq];
    float dv = g_dinv[v];
    float4 bb = ((const float4*)b1)[fq];
    float4 r;
    r.x = fmaxf((s.x + self.x) * dv + bb.x, 0.f) * dv;
    r.y = fmaxf((s.y + self.y) * dv + bb.y, 0.f) * dv;
    r.z = fmaxf((s.z + self.z) * dv + bb.z, 0.f) * dv;
    r.w = fmaxf((s.w + self.w) * dv + bb.w, 0.f) * dv;
    if (slot == 0) ((float4*)g_rs)[(size_t)v * 4 + fq] = r;
}

// Aggregation 2 fused with 16->40 GEMM + log_softmax.
__global__ __launch_bounds__(256) void k_agg2_out(const float* __restrict__ W2,
                                                 const float* __restrict__ b2,
                                                 float* __restrict__ out) {
    __shared__ float W2s[HD * NC];
    int tid = threadIdx.x;
    for (int idx = tid; idx < HD * NC; idx += 256) W2s[idx] = W2[idx];
    __syncthreads();

    int warp = (blockIdx.x * 256 + tid) >> 5;
    if (warp >= NN) return;
    int v = warp;
    int lane = tid & 31;
    int slot = lane >> 2;
    int fq = lane & 3;
    const float4* r4 = (const float4*)g_rs;
    int start = g_off[v], end = g_off[v + 1];
    float4 s = make_float4(0.f, 0.f, 0.f, 0.f);
    float4 s2 = make_float4(0.f, 0.f, 0.f, 0.f);
    int e = start + slot;
    for (; e + 8 < end; e += 16) {
        int sa = g_src[e];
        int sb = g_src[e + 8];
        float4 ha = r4[(size_t)sa * 4 + fq];
        float4 hb = r4[(size_t)sb * 4 + fq];
        s.x += ha.x; s.y += ha.y; s.z += ha.z; s.w += ha.w;
        s2.x += hb.x; s2.y += hb.y; s2.z += hb.z; s2.w += hb.w;
    }
    if (e < end) {
        float4 ha = r4[(size_t)g_src[e] * 4 + fq];
        s.x += ha.x; s.y += ha.y; s.z += ha.z; s.w += ha.w;
    }
    s.x += s2.x; s.y += s2.y; s.z += s2.z; s.w += s2.w;
#pragma unroll
    for (int o = 4; o <= 16; o <<= 1) {
        s.x += __shfl_xor_sync(0xffffffffu, s.x, o);
        s.y += __shfl_xor_sync(0xffffffffu, s.y, o);
        s.z += __shfl_xor_sync(0xffffffffu, s.z, o);
        s.w += __shfl_xor_sync(0xffffffffu, s.w, o);
    }
    float4 self = r4[(size_t)v * 4 + fq];
    float dv = g_dinv[v];
    float4 t4;
    t4.x = (s.x + self.x) * dv;
    t4.y = (s.y + self.y) * dv;
    t4.z = (s.z + self.z) * dv;
    t4.w = (s.w + self.w) * dv;

    float f[16];
#pragma unroll
    for (int q = 0; q < 4; q++) {
        f[4 * q + 0] = __shfl_sync(0xffffffffu, t4.x, q);
        f[4 * q + 1] = __shfl_sync(0xffffffffu, t4.y, q);
        f[4 * q + 2] = __shfl_sync(0xffffffffu, t4.z, q);
        f[4 * q + 3] = __shfl_sync(0xffffffffu, t4.w, q);
    }

    int j0 = lane;
    int j1 = lane + 32;
    bool has1 = (lane < 8);
    float acc0 = b2[j0];
    float acc1 = has1 ? b2[j1] : 0.f;
#pragma unroll
    for (int k = 0; k < 16; k++) {
        acc0 += f[k] * W2s[k * NC + j0];
        float w1v = has1 ? W2s[k * NC + j1] : 0.f;
        acc1 += f[k] * w1v;
    }

    float m = has1 ? fmaxf(acc0, acc1) : acc0;
#pragma unroll
    for (int o = 16; o >= 1; o >>= 1)
        m = fmaxf(m, __shfl_xor_sync(0xffffffffu, m, o));
    float e0 = __expf(acc0 - m);
    float e1 = has1 ? __expf(acc1 - m) : 0.f;
    float sm = e0 + e1;
#pragma unroll
    for (int o = 16; o >= 1; o >>= 1)
        sm += __shfl_xor_sync(0xffffffffu, sm, o);
    float lse = __logf(sm);
    out[(size_t)v * NC + j0] = acc0 - m - lse;
    if (has1) out[(size_t)v * NC + j1] = acc1 - m - lse;
}

// ---------------------------------------------------------------------------
extern "C" void kernel_launch(void* const* d_in, const int* in_sizes, int n_in,
                              void* d_out, int out_size) {
    const float* x  = (const float*)d_in[0];
    const void*  ei = d_in[1];
    const float* W1 = (const float*)d_in[2];
    const float* b1 = (const float*)d_in[3];
    const float* W2 = (const float*)d_in[4];
    const float* b2 = (const float*)d_in[5];
    float* out = (float*)d_out;

    int smem = FIN * 8 * 8 + RPB * QPAD * 16;  // 32768 + 20480 = 53248 B
    static cudaStream_t s_side;
    static cudaEvent_t ev_fork, ev_scan, ev_join;
    static int inited = 0;
    if (!inited) {
        cudaFuncSetAttribute(k_gemm1, cudaFuncAttributeMaxDynamicSharedMemorySize,
                             smem);
        cudaStreamCreateWithFlags(&s_side, cudaStreamNonBlocking);
        cudaEventCreateWithFlags(&ev_fork, cudaEventDisableTiming);
        cudaEventCreateWithFlags(&ev_scan, cudaEventDisableTiming);
        cudaEventCreateWithFlags(&ev_join, cudaEventDisableTiming);
        inited = 1;
    }

    // fork: gemm1 (fma/DRAM) runs concurrently with the CSR build (L2 atomics)
    cudaEventRecord(ev_fork, 0);
    cudaStreamWaitEvent(s_side, ev_fork, 0);
    k_gemm1<<<(NN + RPB - 1) / RPB, TPB_G, smem, s_side>>>(x, W1);

    k_hist<<<(NE / 4 + 255) / 256, 256>>>(ei);
    k_scan_all<<<(NN + 1023) / 1024, 1024>>>();
    cudaEventRecord(ev_scan, 0);  // dinv ready

    k_scatter<<<(NE / 4 + 255) / 256, 256>>>(ei);

    // side stream: scale h1s (needs gemm + dinv), overlapping scatter
    cudaStreamWaitEvent(s_side, ev_scan, 0);
    k_scale<<<(NN * 4 + 255) / 256, 256, 0, s_side>>>();

    // join
    cudaEventRecord(ev_join, s_side);
    cudaStreamWaitEvent(0, ev_join, 0);

    k_agg1<<<(NN + 7) / 8, 256>>>(b1);
    k_agg2_out<<<(NN + 7) / 8, 256>>>(W2, b2, out);
}

// round 14
// speedup vs baseline: 1.0537x; 1.0537x over previous
#include <cuda_runtime.h>
#include <math.h>

#define NN 100000
#define NE 3200000
#define FIN 512
#define HD 16
#define NC 40

#define RPB 256    // rows per gemm block
#define TPB_G 128  // gemm threads per block (2 rows/thread)
#define CH 32      // k-chunk size (8 float4)  [R12 proven config]
#define QPAD 9     // 8 float4 per row + 1 pad -> conflict-free LDS.128

typedef unsigned long long ull;

// ---------------- device scratch (static: no runtime alloc) ----------------
__device__ int   g_deg[NN];          // zero-init by loader; restored each run
__device__ int   g_off[NN + 1];
__device__ int   g_cur[NN];
__device__ int   g_bsum[128];
__device__ int   g_ctr = 0;          // scan arrival counter (self-restoring)
__device__ int   g_ctr2 = 0;         // scan exit counter
__device__ int   g_flag = 0;         // scan middle-phase flag
__device__ int   g_src[NE];
__device__ float g_dinv[NN];
__device__ float g_h1s[NN * HD];
__device__ float g_rs[NN * HD];

// ---------------- f32x2 packed math helpers ----------------
__device__ __forceinline__ ull pk2(float lo, float hi) {
    ull r;
    asm("mov.b64 %0, {%1, %2};" : "=l"(r) : "f"(lo), "f"(hi));
    return r;
}
__device__ __forceinline__ ull fma2(ull a, ull b, ull c) {
    ull d;
    asm("fma.rn.f32x2 %0, %1, %2, %3;" : "=l"(d) : "l"(a), "l"(b), "l"(c));
    return d;
}
__device__ __forceinline__ float2 upk2(ull p) {
    float2 v;
    asm("mov.b64 {%0, %1}, %2;" : "=f"(v.x), "=f"(v.y) : "l"(p));
    return v;
}

// Per-block int32/int64 detection: int64 ids < 2^31 => odd 32-bit words all 0.
__device__ __forceinline__ int detect_is64(const void* ei, int tid) {
    __shared__ int s64;
    if (tid < 32) {
        int w = ((const int*)ei)[2 * tid + 1];
        unsigned nz = __ballot_sync(0xffffffffu, w != 0);
        if (tid == 0) s64 = (nz == 0) ? 1 : 0;
    }
    __syncthreads();
    return s64;
}

// 4 edges per thread histogram of dst (col) array.
__global__ void k_hist(const void* __restrict__ ei) {
    int tid = threadIdx.x;
    int is64 = detect_is64(ei, tid);
    int t = blockIdx.x * 256 + tid;
    if (t >= NE / 4) return;
    int c0, c1, c2, c3;
    if (is64) {
        const longlong2* p = (const longlong2*)((const long long*)ei + NE);
        longlong2 a = p[2 * t];
        longlong2 b = p[2 * t + 1];
        c0 = (int)a.x; c1 = (int)a.y; c2 = (int)b.x; c3 = (int)b.y;
    } else {
        int4 a = ((const int4*)((const int*)ei + NE))[t];
        c0 = a.x; c1 = a.y; c2 = a.z; c3 = a.w;
    }
    atomicAdd(&g_deg[c0], 1);
    atomicAdd(&g_deg[c1], 1);
    atomicAdd(&g_deg[c2], 1);
    atomicAdd(&g_deg[c3], 1);
}

// Single-kernel full scan (single wave, 98 blocks). Re-zeros g_deg and its
// own state (ctr/ctr2/flag) so every graph replay starts clean.
__global__ __launch_bounds__(1024) void k_scan_all() {
    int b = blockIdx.x;
    int i = b * 1024 + threadIdx.x;
    int val = (i < NN) ? g_deg[i] : 0;
    int lane = threadIdx.x & 31, wid = threadIdx.x >> 5;
    int x = val;
#pragma unroll
    for (int o = 1; o < 32; o <<= 1) {
        int y = __shfl_up_sync(0xffffffffu, x, o);
        if (lane >= o) x += y;
    }
    __shared__ int wsum[32];
    __shared__ int amLast;
    if (lane == 31) wsum[wid] = x;
    __syncthreads();
    if (wid == 0) {
        int w = wsum[lane];
#pragma unroll
        for (int o = 1; o < 32; o <<= 1) {
            int y = __shfl_up_sync(0xffffffffu, w, o);
            if (lane >= o) w += y;
        }
        wsum[lane] = w;
    }
    __syncthreads();
    int incl = x + (wid > 0 ? wsum[wid - 1] : 0);
    if (threadIdx.x == 1023) g_bsum[b] = incl;
    __syncthreads();
    if (threadIdx.x == 0) {
        __threadfence();
        amLast = (atomicAdd(&g_ctr, 1) == gridDim.x - 1);
    }
    __syncthreads();
    if (amLast) {
        if (threadIdx.x == 0) __threadfence();
        __syncthreads();
        if (threadIdx.x < 32) {
            int nb = gridDim.x;
            int base = threadIdx.x * 4;
            int v0 = (base + 0 < nb) ? g_bsum[base + 0] : 0;
            int v1 = (base + 1 < nb) ? g_bsum[base + 1] : 0;
            int v2 = (base + 2 < nb) ? g_bsum[base + 2] : 0;
            int v3 = (base + 3 < nb) ? g_bsum[base + 3] : 0;
            int s0 = v0, s1 = s0 + v1, s2 = s1 + v2, s3 = s2 + v3;
            int tot = s3;
            int xs = tot;
#pragma unroll
            for (int o = 1; o < 32; o <<= 1) {
                int y = __shfl_up_sync(0xffffffffu, xs, o);
                if (lane >= o) xs += y;
            }
            int excl = xs - tot;
            g_bsum[base + 0] = s0 + excl;
            g_bsum[base + 1] = s1 + excl;
            g_bsum[base + 2] = s2 + excl;
            g_bsum[base + 3] = s3 + excl;
            __syncwarp();
            if (threadIdx.x == 0) {
                int one = 1;
                asm volatile("st.release.gpu.b32 [%0], %1;" ::"l"(&g_flag),
                             "r"(one) : "memory");
            }
        }
    }
    if (threadIdx.x == 0) {
        int f;
        do {
            asm volatile("ld.acquire.gpu.b32 %0, [%1];" : "=r"(f)
                         : "l"(&g_flag) : "memory");
        } while (f == 0);
    }
    __syncthreads();
    int add = (b > 0) ? g_bsum[b - 1] : 0;
    int fin = incl + add;
    if (i < NN) {
        g_off[i + 1] = fin;
        g_cur[i] = fin - val;
        g_dinv[i] = rsqrtf((float)(val + 1));
        g_deg[i] = 0;  // restore for next replay
    }
    if (i == 0) g_off[0] = 0;
    __syncthreads();
    if (threadIdx.x == 0) {
        if (atomicAdd(&g_ctr2, 1) == gridDim.x - 1) {
            g_ctr = 0;
            g_ctr2 = 0;
            g_flag = 0;
        }
    }
}

// GEMM1 (UNSCALED, R12 proven config): 2 rows/thread, k sequential, W
// warp-uniform in smem, x staged row-major in SMEM with register-prefetch
// pipeline (CH=32, 16 chunks). Side-stream concurrent with CSR build.
__global__ __launch_bounds__(TPB_G) void k_gemm1(const float* __restrict__ x,
                                                 const float* __restrict__ W1) {
    extern __shared__ char sm[];
    ull* Ws = (ull*)sm;                            // 4096 ull = 32KB
    float4* sx = (float4*)(sm + FIN * 8 * 8);      // [RPB][QPAD]
    int tid = threadIdx.x;

    const ull* w64 = (const ull*)W1;  // identity packing: pairs of floats
    for (int i = tid; i < FIN * 8; i += TPB_G) Ws[i] = w64[i];

    int base = blockIdx.x * RPB;
    int r0 = base + tid;
    int r1 = base + tid + TPB_G;

    ull acc0[8], acc1[8];
#pragma unroll
    for (int jp = 0; jp < 8; jp++) { acc0[jp] = 0ull; acc1[jp] = 0ull; }

    const float4* x4 = (const float4*)x;

    // staging map: i = tid + it*TPB_G -> row = i>>3, q = i&7 (coalesced LDG)
    int srow[16], sq[16];
    size_t sgoff[16];
#pragma unroll
    for (int it = 0; it < 16; it++) {
        int i = tid + it * TPB_G;
        srow[it] = i >> 3;
        sq[it] = i & 7;
        int gr = min(base + srow[it], NN - 1);
        sgoff[it] = (size_t)gr * 128 + sq[it];
    }

    float4 pf[16];
#pragma unroll
    for (int it = 0; it < 16; it++) pf[it] = x4[sgoff[it]];

    for (int ch = 0; ch < FIN / CH; ch++) {
        __syncthreads();
#pragma unroll
        for (int it = 0; it < 16; it++)
            sx[srow[it] * QPAD + sq[it]] = pf[it];
        if (ch + 1 < FIN / CH) {
#pragma unroll
            for (int it = 0; it < 16; it++)
                pf[it] = x4[sgoff[it] + (size_t)(ch + 1) * 8];
        }
        __syncthreads();

        const ulonglong2* wrow = (const ulonglong2*)&Ws[ch * CH * 8];
#pragma unroll
        for (int k4 = 0; k4 < CH / 4; k4++) {
            float4 xv0 = sx[tid * QPAD + k4];
            float4 xv1 = sx[(tid + TPB_G) * QPAD + k4];
            float xa0[4] = {xv0.x, xv0.y, xv0.z, xv0.w};
            float xa1[4] = {xv1.x, xv1.y, xv1.z, xv1.w};
#pragma unroll
            for (int c = 0; c < 4; c++) {
                ull xp0 = pk2(xa0[c], xa0[c]);
                ull xp1 = pk2(xa1[c], xa1[c]);
#pragma unroll
                for (int jq = 0; jq < 4; jq++) {
                    ulonglong2 wv = wrow[(k4 * 4 + c) * 4 + jq];  // uniform
                    acc0[2 * jq] = fma2(xp0, wv.x, acc0[2 * jq]);
                    acc0[2 * jq + 1] = fma2(xp0, wv.y, acc0[2 * jq + 1]);
                    acc1[2 * jq] = fma2(xp1, wv.x, acc1[2 * jq]);
                    acc1[2 * jq + 1] = fma2(xp1, wv.y, acc1[2 * jq + 1]);
                }
            }
        }
    }

    if (r0 < NN) {
        float4* o4 = (float4*)&g_h1s[(size_t)r0 * HD];
#pragma unroll
        for (int q = 0; q < 4; q++) {
            float2 a = upk2(acc0[2 * q]);
            float2 b = upk2(acc0[2 * q + 1]);
            o4[q] = make_float4(a.x, a.y, b.x, b.y);
        }
    }
    if (r1 < NN) {
        float4* o4 = (float4*)&g_h1s[(size_t)r1 * HD];
#pragma unroll
        for (int q = 0; q < 4; q++) {
            float2 a = upk2(acc1[2 * q]);
            float2 b = upk2(acc1[2 * q + 1]);
            o4[q] = make_float4(a.x, a.y, b.x, b.y);
        }
    }
}

// Apply dinv scaling to h1s. Runs on the side stream after gemm + scan,
// overlapping scatter on the main stream.
__global__ void k_scale() {
    int i = blockIdx.x * 256 + threadIdx.x;
    if (i >= NN * 4) return;
    float dv = g_dinv[i >> 2];
    float4* p = (float4*)g_h1s;
    float4 v = p[i];
    v.x *= dv; v.y *= dv; v.z *= dv; v.w *= dv;
    p[i] = v;
}

// 4 edges per thread scatter (row into CSR slot of col).
__global__ void k_scatter(const void* __restrict__ ei) {
    int tid = threadIdx.x;
    int is64 = detect_is64(ei, tid);
    int t = blockIdx.x * 256 + tid;
    if (t >= NE / 4) return;
    int r0, r1, r2, r3, c0, c1, c2, c3;
    if (is64) {
        const longlong2* pr = (const longlong2*)((const long long*)ei);
        const longlong2* pc = (const longlong2*)((const long long*)ei + NE);
        longlong2 ra = pr[2 * t], rb = pr[2 * t + 1];
        longlong2 ca = pc[2 * t], cb = pc[2 * t + 1];
        r0 = (int)ra.x; r1 = (int)ra.y; r2 = (int)rb.x; r3 = (int)rb.y;
        c0 = (int)ca.x; c1 = (int)ca.y; c2 = (int)cb.x; c3 = (int)cb.y;
    } else {
        int4 ra = ((const int4*)((const int*)ei))[t];
        int4 ca = ((const int4*)((const int*)ei + NE))[t];
        r0 = ra.x; r1 = ra.y; r2 = ra.z; r3 = ra.w;
        c0 = ca.x; c1 = ca.y; c2 = ca.z; c3 = ca.w;
    }
    g_src[atomicAdd(&g_cur[c0], 1)] = r0;
    g_src[atomicAdd(&g_cur[c1], 1)] = r1;
    g_src[atomicAdd(&g_cur[c2], 1)] = r2;
    g_src[atomicAdd(&g_cur[c3], 1)] = r3;
}

// Aggregation 1: rs[v] = relu((sum_in h1s + h1s[v])*dinv[v] + b1) * dinv[v]
__global__ __launch_bounds__(256) void k_agg1(const float* __restrict__ b1) {
    int warp = (blockIdx.x * 256 + threadIdx.x) >> 5;
    if (warp >= NN) return;
    int v = warp;
    int lane = threadIdx.x & 31;
    int slot = lane >> 2;
    int fq = lane & 3;
    const float4* h4 = (const float4*)g_h1s;
    int start = g_off[v], end = g_off[v + 1];
    float4 s = make_float4(0.f, 0.f, 0.f, 0.f);
    float4 s2 = make_float4(0.f, 0.f, 0.f, 0.f);
    int e = start + slot;
    for (; e + 8 < end; e += 16) {
        int sa = g_src[e];
        int sb = g_src[e + 8];
        float4 ha = h4[(size_t)sa * 4 + fq];
        float4 hb = h4[(size_t)sb * 4 + fq];
        s.x += ha.x; s.y += ha.y; s.z += ha.z; s.w += ha.w;
        s2.x += hb.x; s2.y += hb.y; s2.z += hb.z; s2.w += hb.w;
    }
    if (e < end) {
        float4 ha = h4[(size_t)g_src[e] * 4 + fq];
        s.x += ha.x; s.y += ha.y; s.z += ha.z; s.w += ha.w;
    }
    s.x += s2.x; s.y += s2.y; s.z += s2.z; s.w += s2.w;
#pragma unroll
    for (int o = 4; o <= 16; o <<= 1) {
        s.x += __shfl_xor_sync(0xffffffffu, s.x, o);
        s.y += __shfl_xor_sync(0xffffffffu, s.y, o);
        s.z += __shfl_xor_sync(0xffffffffu, s.z, o);
        s.w += __shfl_xor_sync(0xffffffffu, s.w, o);
    }
    float4 self = h4[(size_t)v * 4 + fq];
    float dv = g_dinv[v];
    float4 bb = ((const float4*)b1)[fq];
    float4 r;
    r.x = fmaxf((s.x + self.x) * dv + bb.x, 0.f) * dv;
    r.y = fmaxf((s.y + self.y) * dv + bb.y, 0.f) * dv;
    r.z = fmaxf((s.z + self.z) * dv + bb.z, 0.f) * dv;
    r.w = fmaxf((s.w + self.w) * dv + bb.w, 0.f) * dv;
    if (slot == 0) ((float4*)g_rs)[(size_t)v * 4 + fq] = r;
}

// Aggregation 2 fused with 16->40 GEMM + log_softmax.
__global__ __launch_bounds__(256) void k_agg2_out(const float* __restrict__ W2,
                                                 const float* __restrict__ b2,
                                                 float* __restrict__ out) {
    __shared__ float W2s[HD * NC];
    int tid = threadIdx.x;
    for (int idx = tid; idx < HD * NC; idx += 256) W2s[idx] = W2[idx];
    __syncthreads();

    int warp = (blockIdx.x * 256 + tid) >> 5;
    if (warp >= NN) return;
    int v = warp;
    int lane = tid & 31;
    int slot = lane >> 2;
    int fq = lane & 3;
    const float4* r4 = (const float4*)g_rs;
    int start = g_off[v], end = g_off[v + 1];
    float4 s = make_float4(0.f, 0.f, 0.f, 0.f);
    float4 s2 = make_float4(0.f, 0.f, 0.f, 0.f);
    int e = start + slot;
    for (; e + 8 < end; e += 16) {
        int sa = g_src[e];
        int sb = g_src[e + 8];
        float4 ha = r4[(size_t)sa * 4 + fq];
        float4 hb = r4[(size_t)sb * 4 + fq];
        s.x += ha.x; s.y += ha.y; s.z += ha.z; s.w += ha.w;
        s2.x += hb.x; s2.y += hb.y; s2.z += hb.z; s2.w += hb.w;
    }
    if (e < end) {
        float4 ha = r4[(size_t)g_src[e] * 4 + fq];
        s.x += ha.x; s.y += ha.y; s.z += ha.z; s.w += ha.w;
    }
    s.x += s2.x; s.y += s2.y; s.z += s2.z; s.w += s2.w;
#pragma unroll
    for (int o = 4; o <= 16; o <<= 1) {
        s.x += __shfl_xor_sync(0xffffffffu, s.x, o);
        s.y += __shfl_xor_sync(0xffffffffu, s.y, o);
        s.z += __shfl_xor_sync(0xffffffffu, s.z, o);
        s.w += __shfl_xor_sync(0xffffffffu, s.w, o);
    }
    float4 self = r4[(size_t)v * 4 + fq];
    float dv = g_dinv[v];
    float4 t4;
    t4.x = (s.x + self.x) * dv;
    t4.y = (s.y + self.y) * dv;
    t4.z = (s.z + self.z) * dv;
    t4.w = (s.w + self.w) * dv;

    float f[16];
#pragma unroll
    for (int q = 0; q < 4; q++) {
        f[4 * q + 0] = __shfl_sync(0xffffffffu, t4.x, q);
        f[4 * q + 1] = __shfl_sync(0xffffffffu, t4.y, q);
        f[4 * q + 2] = __shfl_sync(0xffffffffu, t4.z, q);
        f[4 * q + 3] = __shfl_sync(0xffffffffu, t4.w, q);
    }

    int j0 = lane;
    int j1 = lane + 32;
    bool has1 = (lane < 8);
    float acc0 = b2[j0];
    float acc1 = has1 ? b2[j1] : 0.f;
#pragma unroll
    for (int k = 0; k < 16; k++) {
        acc0 += f[k] * W2s[k * NC + j0];
        float w1v = has1 ? W2s[k * NC + j1] : 0.f;
        acc1 += f[k] * w1v;
    }

    float m = has1 ? fmaxf(acc0, acc1) : acc0;
#pragma unroll
    for (int o = 16; o >= 1; o >>= 1)
        m = fmaxf(m, __shfl_xor_sync(0xffffffffu, m, o));
    float e0 = __expf(acc0 - m);
    float e1 = has1 ? __expf(acc1 - m) : 0.f;
    float sm = e0 + e1;
#pragma unroll
    for (int o = 16; o >= 1; o >>= 1)
        sm += __shfl_xor_sync(0xffffffffu, sm, o);
    float lse = __logf(sm);
    out[(size_t)v * NC + j0] = acc0 - m - lse;
    if (has1) out[(size_t)v * NC + j1] = acc1 - m - lse;
}

// ---------------------------------------------------------------------------
extern "C" void kernel_launch(void* const* d_in, const int* in_sizes, int n_in,
                              void* d_out, int out_size) {
    const float* x  = (const float*)d_in[0];
    const void*  ei = d_in[1];
    const float* W1 = (const float*)d_in[2];
    const float* b1 = (const float*)d_in[3];
    const float* W2 = (const float*)d_in[4];
    const float* b2 = (const float*)d_in[5];
    float* out = (float*)d_out;

    int smem = FIN * 8 * 8 + RPB * QPAD * 16;  // 32768 + 36864 = 69632 B
    static cudaStream_t s_side;
    static cudaEvent_t ev_fork, ev_scan, ev_join;
    static int inited = 0;
    if (!inited) {
        cudaFuncSetAttribute(k_gemm1, cudaFuncAttributeMaxDynamicSharedMemorySize,
                             smem);
        cudaStreamCreateWithFlags(&s_side, cudaStreamNonBlocking);
        cudaEventCreateWithFlags(&ev_fork, cudaEventDisableTiming);
        cudaEventCreateWithFlags(&ev_scan, cudaEventDisableTiming);
        cudaEventCreateWithFlags(&ev_join, cudaEventDisableTiming);
        inited = 1;
    }

    // fork: gemm1 (fma/DRAM) runs concurrently with the CSR build (L2 atomics)
    cudaEventRecord(ev_fork, 0);
    cudaStreamWaitEvent(s_side, ev_fork, 0);
    k_gemm1<<<(NN + RPB - 1) / RPB, TPB_G, smem, s_side>>>(x, W1);

    k_hist<<<(NE / 4 + 255) / 256, 256>>>(ei);
    k_scan_all<<<(NN + 1023) / 1024, 1024>>>();
    cudaEventRecord(ev_scan, 0);  // dinv ready

    k_scatter<<<(NE / 4 + 255) / 256, 256>>>(ei);

    // side stream: scale h1s (needs gemm + dinv), overlapping scatter
    cudaStreamWaitEvent(s_side, ev_scan, 0);
    k_scale<<<(NN * 4 + 255) / 256, 256, 0, s_side>>>();

    // join
    cudaEventRecord(ev_join, s_side);
    cudaStreamWaitEvent(0, ev_join, 0);

    k_agg1<<<(NN + 7) / 8, 256>>>(b1);
    k_agg2_out<<<(NN + 7) / 8, 256>>>(W2, b2, out);
}